// round 9
// baseline (speedup 1.0000x reference)
#include <cuda_runtime.h>
#include <cstdint>

// MLLoss: per-sample hinge loss over [B,16] f32 distances -> scalar mean.
// Labels int32. 288 MB logical read; all LDG variants cap at ~6.3 TB/s.
//
// R9: TMA (cp.async.bulk) double-buffered pipeline — bypasses the L1tex/LDG
// path to test whether the 6.3 TB/s plateau is an LDG queueing artifact.
// 256-row chunks (16KB dist + 1KB + 1KB labels) staged into smem, mbarrier
// complete_tx sync, compute = conflict-free LDS.128 (4-lane groups) with the
// shuffle-free decomposition (gate*quarter-hinge + leader row-term), labels
// via smem broadcast. 912 blocks = one wave at 6 blocks/SM (smem-limited).

#define THREADS 256
#define BLOCKS  912                 // 6 blocks/SM x 152 SMs
#define ROWS_PC 256                 // rows per chunk
#define DIST_BYTES (ROWS_PC * 64)   // 16384
#define LBL_BYTES  (ROWS_PC * 4)    // 1024
#define STAGE_BYTES (DIST_BYTES + 2 * LBL_BYTES)

__device__ float        g_partial;
__device__ unsigned int g_count;

__device__ __forceinline__ uint32_t smem_u32(const void* p) {
    uint32_t a;
    asm("{ .reg .u64 t; cvta.to.shared.u64 t, %1; cvt.u32.u64 %0, t; }"
        : "=r"(a) : "l"(p));
    return a;
}

__device__ __forceinline__ void mbar_init(uint32_t mbar, uint32_t count) {
    asm volatile("mbarrier.init.shared.b64 [%0], %1;" :: "r"(mbar), "r"(count) : "memory");
}
__device__ __forceinline__ void mbar_expect_tx(uint32_t mbar, uint32_t bytes) {
    asm volatile("mbarrier.arrive.expect_tx.shared.b64 _, [%0], %1;"
                 :: "r"(mbar), "r"(bytes) : "memory");
}
__device__ __forceinline__ void mbar_wait(uint32_t mbar, uint32_t parity) {
    uint32_t done;
    asm volatile(
        "{ .reg .pred p;\n"
        "  mbarrier.try_wait.parity.acquire.cta.shared::cta.b64 p, [%1], %2;\n"
        "  selp.b32 %0, 1, 0, p; }"
        : "=r"(done) : "r"(mbar), "r"(parity) : "memory");
    if (!done) {
        asm volatile(
            "{ .reg .pred P;\n"
            "WL_%=:\n"
            "  mbarrier.try_wait.parity.acquire.cta.shared::cta.b64 P, [%0], %1, 0x989680;\n"
            "  @P bra.uni WD_%=;\n"
            "  bra.uni WL_%=;\n"
            "WD_%=: }"
            :: "r"(mbar), "r"(parity) : "memory");
    }
}
__device__ __forceinline__ void bulk_g2s(uint32_t dst, const void* src,
                                         uint32_t bytes, uint32_t mbar) {
    asm volatile(
        "cp.async.bulk.shared::cta.global.mbarrier::complete_tx::bytes [%0], [%1], %2, [%3];"
        :: "r"(dst), "l"(src), "r"(bytes), "r"(mbar) : "memory");
}

__global__ __launch_bounds__(THREADS)
void mlloss_tma_kernel(const float* __restrict__ dist,   // [B,16] f32
                       const int* __restrict__ doctor,   // [B]
                       const int* __restrict__ real_l,   // [B]
                       float* __restrict__ out,
                       int B, float inv_B)
{
    __shared__ __align__(128) unsigned char sm_dist[2][DIST_BYTES];
    __shared__ __align__(16)  int sm_doc[2][ROWS_PC];
    __shared__ __align__(16)  int sm_real[2][ROWS_PC];
    __shared__ __align__(8)   unsigned long long sm_mbar[2];
    __shared__ float warp_sums[THREADS / 32];

    const int tid  = threadIdx.x;
    const int lane = tid & 31;
    const int warp = tid >> 5;
    const int G    = gridDim.x;
    const int nchunks = B / ROWS_PC;

    const uint32_t mbar0 = smem_u32(&sm_mbar[0]);
    const uint32_t mbar1 = smem_u32(&sm_mbar[1]);
    const uint32_t d0u   = smem_u32(&sm_dist[0][0]);
    const uint32_t d1u   = smem_u32(&sm_dist[1][0]);
    const uint32_t doc0u = smem_u32(&sm_doc[0][0]);
    const uint32_t doc1u = smem_u32(&sm_doc[1][0]);
    const uint32_t re0u  = smem_u32(&sm_real[0][0]);
    const uint32_t re1u  = smem_u32(&sm_real[1][0]);

    if (tid == 0) {
        mbar_init(mbar0, 1);
        mbar_init(mbar1, 1);
    }
    __syncthreads();

    // prologue: fill both stages
    if (tid == 0) {
        const int c0 = blockIdx.x;
        if (c0 < nchunks) {
            mbar_expect_tx(mbar0, STAGE_BYTES);
            bulk_g2s(d0u,   (const char*)dist   + (size_t)c0 * DIST_BYTES, DIST_BYTES, mbar0);
            bulk_g2s(doc0u, (const char*)doctor + (size_t)c0 * LBL_BYTES,  LBL_BYTES,  mbar0);
            bulk_g2s(re0u,  (const char*)real_l + (size_t)c0 * LBL_BYTES,  LBL_BYTES,  mbar0);
        }
        const int c1 = blockIdx.x + G;
        if (c1 < nchunks) {
            mbar_expect_tx(mbar1, STAGE_BYTES);
            bulk_g2s(d1u,   (const char*)dist   + (size_t)c1 * DIST_BYTES, DIST_BYTES, mbar1);
            bulk_g2s(doc1u, (const char*)doctor + (size_t)c1 * LBL_BYTES,  LBL_BYTES,  mbar1);
            bulk_g2s(re1u,  (const char*)real_l + (size_t)c1 * LBL_BYTES,  LBL_BYTES,  mbar1);
        }
    }

    float acc = 0.0f;
    const int  qg     = lane >> 2;        // row within 8-row group
    const bool is_c0  = (lane & 3) == 0;  // holds cols 0..3

    int ph0 = 0, ph1 = 0;
    int i = 0;
    for (int c = blockIdx.x; c < nchunks; c += G, ++i) {
        const int s = i & 1;
        if (s == 0) { mbar_wait(mbar0, ph0); ph0 ^= 1; }
        else        { mbar_wait(mbar1, ph1); ph1 ^= 1; }

        const float4* dsm = (const float4*)sm_dist[s];
        const int*    doc = sm_doc[s];
        const int*    rel = sm_real[s];

        // warp handles rows [warp*32, warp*32+32): 4 passes of 8 rows
        #pragma unroll
        for (int p = 0; p < 4; p++) {
            const int rb = warp * 32 + p * 8;          // row base in chunk
            const float4 x = dsm[rb * 4 + lane];       // conflict-free LDS.128
            const int r  = rb + qg;                    // this lane's row
            const int dl = doc[r];                      // 4-lane broadcast LDS
            const int rl = rel[r];

            const float h0 = fmaxf(1.0f - x.x, 0.0f);
            const float h1 = fmaxf(1.0f - x.y, 0.0f);
            const float h2 = fmaxf(1.0f - x.z, 0.0f);
            const float h3 = fmaxf(1.0f - x.w, 0.0f);
            const float s4 = (h0 + h1) + (h2 + h3);

            acc += (dl <= 1) ? s4 : 0.0f;              // quarter of row hinge sum
            if (is_c0) {                                // row term from own regs
                acc += (dl == 0) ? (x.x - h0)
                     : (dl == 1) ? (x.y - h1)
                                 : ((rl == 0) ? h1 : h0);
            }
        }

        __syncthreads();                                // all reads of stage s done

        const int cref = c + 2 * G;                     // refill this stage
        if (tid == 0 && cref < nchunks) {
            if (s == 0) {
                mbar_expect_tx(mbar0, STAGE_BYTES);
                bulk_g2s(d0u,   (const char*)dist   + (size_t)cref * DIST_BYTES, DIST_BYTES, mbar0);
                bulk_g2s(doc0u, (const char*)doctor + (size_t)cref * LBL_BYTES,  LBL_BYTES,  mbar0);
                bulk_g2s(re0u,  (const char*)real_l + (size_t)cref * LBL_BYTES,  LBL_BYTES,  mbar0);
            } else {
                mbar_expect_tx(mbar1, STAGE_BYTES);
                bulk_g2s(d1u,   (const char*)dist   + (size_t)cref * DIST_BYTES, DIST_BYTES, mbar1);
                bulk_g2s(doc1u, (const char*)doctor + (size_t)cref * LBL_BYTES,  LBL_BYTES,  mbar1);
                bulk_g2s(re1u,  (const char*)real_l + (size_t)cref * LBL_BYTES,  LBL_BYTES,  mbar1);
            }
        }
    }

    // tail rows (B % 256) — scalar LDG, block 0 only
    const int tail_start = nchunks * ROWS_PC;
    if (blockIdx.x == 0) {
        for (int row = tail_start + tid; row < B; row += blockDim.x) {
            const float4* d4 = (const float4*)(dist + (size_t)row * 16);
            const float4 a = d4[0], b = d4[1], cc = d4[2], dd = d4[3];
            const float h0 = fmaxf(1.0f - a.x, 0.0f);
            const float h1 = fmaxf(1.0f - a.y, 0.0f);
            float hs = h0 + h1
                     + fmaxf(1.0f - a.z, 0.0f)  + fmaxf(1.0f - a.w, 0.0f)
                     + fmaxf(1.0f - b.x, 0.0f)  + fmaxf(1.0f - b.y, 0.0f)
                     + fmaxf(1.0f - b.z, 0.0f)  + fmaxf(1.0f - b.w, 0.0f)
                     + fmaxf(1.0f - cc.x, 0.0f) + fmaxf(1.0f - cc.y, 0.0f)
                     + fmaxf(1.0f - cc.z, 0.0f) + fmaxf(1.0f - cc.w, 0.0f)
                     + fmaxf(1.0f - dd.x, 0.0f) + fmaxf(1.0f - dd.y, 0.0f)
                     + fmaxf(1.0f - dd.z, 0.0f) + fmaxf(1.0f - dd.w, 0.0f);
            const int dlv = doctor[row], rlv = real_l[row];
            acc += (dlv == 0) ? (a.x + hs - h0)
                 : (dlv == 1) ? (a.y + hs - h1)
                              : ((rlv == 0) ? h1 : h0);
        }
    }

    // warp reduce
    #pragma unroll
    for (int off = 16; off > 0; off >>= 1)
        acc += __shfl_xor_sync(0xFFFFFFFFu, acc, off);
    if (lane == 0) warp_sums[warp] = acc;
    __syncthreads();

    if (warp == 0) {
        float v = (lane < THREADS / 32) ? warp_sums[lane] : 0.0f;
        #pragma unroll
        for (int off = 16; off > 0; off >>= 1)
            v += __shfl_xor_sync(0xFFFFFFFFu, v, off);

        if (lane == 0) {
            atomicAdd(&g_partial, v);
            __threadfence();
            const unsigned int ticket = atomicAdd(&g_count, 1u);
            if (ticket == gridDim.x - 1) {
                const float total = atomicAdd(&g_partial, 0.0f); // fenced read
                out[0] = total * inv_B;
                g_partial = 0.0f;
                g_count   = 0u;
                __threadfence();
            }
        }
    }
}

extern "C" void kernel_launch(void* const* d_in, const int* in_sizes, int n_in,
                              void* d_out, int out_size)
{
    const float* dist   = (const float*)d_in[0];
    const int*   doctor = (const int*)d_in[1];
    const int*   real_l = (const int*)d_in[2];
    float*       out    = (float*)d_out;

    const int B = in_sizes[1];
    const float inv_B = 1.0f / (float)B;

    mlloss_tma_kernel<<<BLOCKS, THREADS>>>(dist, doctor, real_l, out, B, inv_B);
}

// round 10
// speedup vs baseline: 1.0284x; 1.0284x over previous
#include <cuda_runtime.h>
#include <cuda_bf16.h>

// MLLoss: per-sample hinge loss over [B,16] f32 distances -> scalar mean.
// Labels int32. Memory-floor-bound: 288 MB read; all access paths
// (strided/coalesced/predicated LDG, TMA bulk) plateau at 6.0-6.3 TB/s.
//
// R10 = R6 (best: 49.6us, 6322 GB/s) + L2::256B prefetch hint on the
// distance loads: fetch 256B granules from DRAM per miss to amortize
// row/command overhead on this perfectly-sequential stream. Zero extra
// instructions; everything else identical to R6.

#define THREADS 256
#define BLOCKS  1216   // 8 blocks/SM x 152 SMs = one full wave

__device__ float        g_partial;   // zero at load; reset by last block each call
__device__ unsigned int g_count;

__device__ __forceinline__ float4 ldcs_256(const float4* p) {
    float4 v;
    asm("ld.global.cs.L2::256B.v4.f32 {%0,%1,%2,%3}, [%4];"
        : "=f"(v.x), "=f"(v.y), "=f"(v.z), "=f"(v.w) : "l"(p));
    return v;
}

__global__ __launch_bounds__(THREADS, 8)
void mlloss_kernel(const float4* __restrict__ dist4,  // [B,16] as B*4 float4
                   const int* __restrict__ doctor,    // [B] int32 {0,1,2}
                   const int* __restrict__ real_l,    // [B] int32 {0,1}
                   float* __restrict__ out,
                   int B, float inv_B)
{
    const int tid    = blockIdx.x * blockDim.x + threadIdx.x;
    const int stride = gridDim.x * blockDim.x;

    float acc = 0.0f;

    for (int row = tid; row < B; row += stride) {
        const size_t base = (size_t)row * 4;
        const float4 a = ldcs_256(&dist4[base + 0]);
        const float4 b = ldcs_256(&dist4[base + 1]);
        const float4 c = ldcs_256(&dist4[base + 2]);
        const float4 d = ldcs_256(&dist4[base + 3]);
        const int   dl = __ldcs(&doctor[row]);
        const int   rl = __ldcs(&real_l[row]);

        const float h0 = fmaxf(1.0f - a.x, 0.0f);
        const float h1 = fmaxf(1.0f - a.y, 0.0f);
        float hs = h0 + h1
                 + fmaxf(1.0f - a.z, 0.0f) + fmaxf(1.0f - a.w, 0.0f)
                 + fmaxf(1.0f - b.x, 0.0f) + fmaxf(1.0f - b.y, 0.0f)
                 + fmaxf(1.0f - b.z, 0.0f) + fmaxf(1.0f - b.w, 0.0f)
                 + fmaxf(1.0f - c.x, 0.0f) + fmaxf(1.0f - c.y, 0.0f)
                 + fmaxf(1.0f - c.z, 0.0f) + fmaxf(1.0f - c.w, 0.0f)
                 + fmaxf(1.0f - d.x, 0.0f) + fmaxf(1.0f - d.y, 0.0f)
                 + fmaxf(1.0f - d.z, 0.0f) + fmaxf(1.0f - d.w, 0.0f);

        const float loss = (dl == 0) ? (a.x + hs - h0)
                         : (dl == 1) ? (a.y + hs - h1)
                                     : ((rl == 0) ? h1 : h0);
        acc += loss;
    }

    // warp reduce
    #pragma unroll
    for (int off = 16; off > 0; off >>= 1)
        acc += __shfl_xor_sync(0xFFFFFFFFu, acc, off);

    __shared__ float warp_sums[THREADS / 32];
    const int lane = threadIdx.x & 31;
    const int wid  = threadIdx.x >> 5;
    if (lane == 0) warp_sums[wid] = acc;
    __syncthreads();

    if (wid == 0) {
        float v = (lane < THREADS / 32) ? warp_sums[lane] : 0.0f;
        #pragma unroll
        for (int off = 16; off > 0; off >>= 1)
            v += __shfl_xor_sync(0xFFFFFFFFu, v, off);

        if (lane == 0) {
            atomicAdd(&g_partial, v);
            __threadfence();
            const unsigned int ticket = atomicAdd(&g_count, 1u);
            if (ticket == gridDim.x - 1) {
                const float total = atomicAdd(&g_partial, 0.0f); // fenced read
                out[0] = total * inv_B;
                g_partial = 0.0f;
                g_count   = 0u;
                __threadfence();
            }
        }
    }
}

extern "C" void kernel_launch(void* const* d_in, const int* in_sizes, int n_in,
                              void* d_out, int out_size)
{
    const float4* dist4  = (const float4*)d_in[0];
    const int*    doctor = (const int*)d_in[1];
    const int*    real_l = (const int*)d_in[2];
    float*        out    = (float*)d_out;

    const int B = in_sizes[1];
    const float inv_B = 1.0f / (float)B;

    mlloss_kernel<<<BLOCKS, THREADS>>>(dist4, doctor, real_l, out, B, inv_B);
}